// round 2
// baseline (speedup 1.0000x reference)
#include <cuda_runtime.h>

// Problem shape (fixed by the dataset):
// x: (B=8, C=64, T=2048, J=64) fp32; Ci=32.
// Inputs (metadata order): x, w_g, b_g, w_theta, b_theta, w_phi, b_phi, proj, w_out, b_out

#define TT 8   // t-values per CTA

// Precomputed fused weights:
//   Q[j,k]  = sum_c proj[j,c]    * w_theta[c,k]      (theta conv folded into projection)
//   R[j,k]  = sum_c proj[j,32+c] * w_phi[c,k]        (phi conv folded into projection)
//   ab[j]   = sum_c proj[j,c]*b_theta[c] + proj[j,32+c]*b_phi[c]
__device__ float g_Qd[64 * 64];
__device__ float g_Rd[64 * 64];
__device__ float g_abd[64];

__global__ void prep_kernel(const float* __restrict__ w_theta,
                            const float* __restrict__ b_theta,
                            const float* __restrict__ w_phi,
                            const float* __restrict__ b_phi,
                            const float* __restrict__ proj) {
    const int tid = threadIdx.x;
    for (int idx = tid; idx < 4096; idx += 256) {
        const int j = idx >> 6, k = idx & 63;
        float q = 0.f, r = 0.f;
#pragma unroll
        for (int c = 0; c < 32; c++) {
            q += proj[j * 64 + c]      * w_theta[c * 64 + k];
            r += proj[j * 64 + 32 + c] * w_phi[c * 64 + k];
        }
        g_Qd[idx] = q;
        g_Rd[idx] = r;
    }
    if (tid < 64) {
        float s = 0.f;
#pragma unroll
        for (int c = 0; c < 32; c++)
            s += proj[tid * 64 + c] * b_theta[c] + proj[tid * 64 + 32 + c] * b_phi[c];
        g_abd[tid] = s;
    }
}

// Shared-memory layout (floats)
#define OFF_RT  0        // Rt [64][68]   Rt[k][j] = R[j][k]
#define OFF_Q   4352     // Qs [64][65]   Qs[j][k]
#define OFF_WGT 8512     // Wgt[64][36]   Wgt[k][o] = w_g[o][k]
#define OFF_WOT 10816    // Wot[32][68]   Wot[o][c] = w_out[c][o]
#define OFF_XS  12992    // xs [64][64]   xs[c][j]
#define OFF_FT  17088    // ft [64][68]   ft[i][j]  = f[j][i]   (f scaled by 1/64)
#define OFF_GT  21440    // gt [64][36]   gt[i][o]  = g[o][i]
#define OFF_YT  23744    // yt [32][68]   yt[o][j]  = y[j][o]
#define OFF_A   25920    // a  [64]
#define OFF_BG  25984    // b_g[32]
#define OFF_BO  26016    // b_out[64]
#define SMEM_FLOATS 26080
#define SMEM_BYTES (SMEM_FLOATS * 4)

__global__ __launch_bounds__(256, 2)
void tnl_kernel(const float* __restrict__ x,
                const float* __restrict__ w_g,
                const float* __restrict__ b_g,
                const float* __restrict__ w_out,
                const float* __restrict__ b_out,
                float* __restrict__ out) {
    extern __shared__ float sm[];
    float* Rt  = sm + OFF_RT;
    float* Qs  = sm + OFF_Q;
    float* Wgt = sm + OFF_WGT;
    float* Wot = sm + OFF_WOT;
    float* xs  = sm + OFF_XS;
    float* ft  = sm + OFF_FT;
    float* gt  = sm + OFF_GT;
    float* yt  = sm + OFF_YT;
    float* avec = sm + OFF_A;
    float* bgs = sm + OFF_BG;
    float* bos = sm + OFF_BO;

    const int tid = threadIdx.x;

    // ---- load constants (once per CTA) ----
    for (int idx = tid; idx < 4096; idx += 256) {
        const int j = idx >> 6, k = idx & 63;
        Rt[k * 68 + j] = g_Rd[idx];
        Qs[j * 65 + k] = g_Qd[idx];
    }
    for (int idx = tid; idx < 2048; idx += 256) {
        const int o = idx >> 6, k = idx & 63;
        Wgt[k * 36 + o] = w_g[idx];          // w_g[o][k]
        const int c = idx >> 5, o2 = idx & 31;
        Wot[o2 * 68 + c] = w_out[idx];       // w_out[c][o2]
    }
    if (tid < 32) bgs[tid] = b_g[tid];
    if (tid < 64) bos[tid] = b_out[tid];
    __syncthreads();

    const int bIdx = blockIdx.x >> 8;            // 256 t-chunks per batch
    const int t0 = (blockIdx.x & 255) * TT;

    for (int tt = 0; tt < TT; tt++) {
        const int t = t0 + tt;

        // ---- load x tile: xs[c][j] = x[b,c,t,j] ----
        {
            const int f4 = tid & 15;
#pragma unroll
            for (int it = 0; it < 4; it++) {
                const int c = (tid >> 4) + it * 16;
                const float4 v = *(const float4*)(x + (((size_t)(bIdx * 64 + c) * 2048 + t) << 6) + f4 * 4);
                *(float4*)(xs + c * 64 + f4 * 4) = v;
            }
        }
        __syncthreads();

        // ---- phase 1: g = W_g @ x + b_g (threads 0..127), a[j] (threads 128..191) ----
        if (tid < 128) {
            const int i0 = (tid & 15) * 4;
            const int o0 = (tid >> 4) * 4;
            float acc[4][4] = {};
#pragma unroll 4
            for (int k = 0; k < 64; k++) {
                const float4 wv = *(const float4*)(Wgt + k * 36 + o0);
                const float4 xv = *(const float4*)(xs + k * 64 + i0);
                acc[0][0] += wv.x * xv.x; acc[0][1] += wv.x * xv.y; acc[0][2] += wv.x * xv.z; acc[0][3] += wv.x * xv.w;
                acc[1][0] += wv.y * xv.x; acc[1][1] += wv.y * xv.y; acc[1][2] += wv.y * xv.z; acc[1][3] += wv.y * xv.w;
                acc[2][0] += wv.z * xv.x; acc[2][1] += wv.z * xv.y; acc[2][2] += wv.z * xv.z; acc[2][3] += wv.z * xv.w;
                acc[3][0] += wv.w * xv.x; acc[3][1] += wv.w * xv.y; acc[3][2] += wv.w * xv.z; acc[3][3] += wv.w * xv.w;
            }
            const float b0 = bgs[o0], b1 = bgs[o0 + 1], b2 = bgs[o0 + 2], b3 = bgs[o0 + 3];
#pragma unroll
            for (int bc = 0; bc < 4; bc++) {
                float4 v;
                v.x = acc[0][bc] + b0; v.y = acc[1][bc] + b1;
                v.z = acc[2][bc] + b2; v.w = acc[3][bc] + b3;
                *(float4*)(gt + (i0 + bc) * 36 + o0) = v;   // gt[i][o]
            }
        } else if (tid < 192) {
            const int j = tid - 128;
            float s = g_abd[j];
#pragma unroll 8
            for (int k = 0; k < 64; k++)
                s += Qs[j * 65 + k] * xs[k * 64 + j];
            avec[j] = s;
        }
        __syncthreads();

        // ---- phase 2: f[j][i] = relu(a[j] + (R@x)[j][i]) / 64, stored transposed ----
        {
            const int i0 = (tid & 15) * 4;
            const int j0 = (tid >> 4) * 4;
            float acc[4][4] = {};
#pragma unroll 4
            for (int k = 0; k < 64; k++) {
                const float4 rv = *(const float4*)(Rt + k * 68 + j0);
                const float4 xv = *(const float4*)(xs + k * 64 + i0);
                acc[0][0] += rv.x * xv.x; acc[0][1] += rv.x * xv.y; acc[0][2] += rv.x * xv.z; acc[0][3] += rv.x * xv.w;
                acc[1][0] += rv.y * xv.x; acc[1][1] += rv.y * xv.y; acc[1][2] += rv.y * xv.z; acc[1][3] += rv.y * xv.w;
                acc[2][0] += rv.z * xv.x; acc[2][1] += rv.z * xv.y; acc[2][2] += rv.z * xv.z; acc[2][3] += rv.z * xv.w;
                acc[3][0] += rv.w * xv.x; acc[3][1] += rv.w * xv.y; acc[3][2] += rv.w * xv.z; acc[3][3] += rv.w * xv.w;
            }
            const float a0 = avec[j0], a1 = avec[j0 + 1], a2 = avec[j0 + 2], a3 = avec[j0 + 3];
#pragma unroll
            for (int bc = 0; bc < 4; bc++) {
                float4 v;
                v.x = fmaxf(acc[0][bc] + a0, 0.f) * 0.015625f;
                v.y = fmaxf(acc[1][bc] + a1, 0.f) * 0.015625f;
                v.z = fmaxf(acc[2][bc] + a2, 0.f) * 0.015625f;
                v.w = fmaxf(acc[3][bc] + a3, 0.f) * 0.015625f;
                *(float4*)(ft + (i0 + bc) * 68 + j0) = v;   // ft[i][j]
            }
        }
        __syncthreads();

        // ---- phase 3: y[j][o] = sum_i f[j][i] * g[o][i], stored transposed ----
        {
            const int o0 = (tid & 15) * 2;
            const int j0 = (tid >> 4) * 4;
            float acc[4][2] = {};
#pragma unroll 4
            for (int k = 0; k < 64; k++) {
                const float4 fv = *(const float4*)(ft + k * 68 + j0);
                const float2 gv = *(const float2*)(gt + k * 36 + o0);
                acc[0][0] += fv.x * gv.x; acc[0][1] += fv.x * gv.y;
                acc[1][0] += fv.y * gv.x; acc[1][1] += fv.y * gv.y;
                acc[2][0] += fv.z * gv.x; acc[2][1] += fv.z * gv.y;
                acc[3][0] += fv.w * gv.x; acc[3][1] += fv.w * gv.y;
            }
#pragma unroll
            for (int bc = 0; bc < 2; bc++) {
                float4 v;
                v.x = acc[0][bc]; v.y = acc[1][bc]; v.z = acc[2][bc]; v.w = acc[3][bc];
                *(float4*)(yt + (o0 + bc) * 68 + j0) = v;   // yt[o][j]
            }
        }
        __syncthreads();

        // ---- phase 4: out[c][j] = sum_o W_out[c][o]*y[j][o] + b_out[c] + x[c][j] ----
        {
            const int j0 = (tid & 15) * 4;
            const int c0 = (tid >> 4) * 4;
            float acc[4][4] = {};
#pragma unroll 4
            for (int o = 0; o < 32; o++) {
                const float4 wv = *(const float4*)(Wot + o * 68 + c0);
                const float4 yv = *(const float4*)(yt + o * 68 + j0);
                acc[0][0] += wv.x * yv.x; acc[0][1] += wv.x * yv.y; acc[0][2] += wv.x * yv.z; acc[0][3] += wv.x * yv.w;
                acc[1][0] += wv.y * yv.x; acc[1][1] += wv.y * yv.y; acc[1][2] += wv.y * yv.z; acc[1][3] += wv.y * yv.w;
                acc[2][0] += wv.z * yv.x; acc[2][1] += wv.z * yv.y; acc[2][2] += wv.z * yv.z; acc[2][3] += wv.z * yv.w;
                acc[3][0] += wv.w * yv.x; acc[3][1] += wv.w * yv.y; acc[3][2] += wv.w * yv.z; acc[3][3] += wv.w * yv.w;
            }
#pragma unroll
            for (int a = 0; a < 4; a++) {
                const int c = c0 + a;
                const float bo = bos[c];
                const float4 xv = *(const float4*)(xs + c * 64 + j0);
                float4 v;
                v.x = acc[a][0] + bo + xv.x;
                v.y = acc[a][1] + bo + xv.y;
                v.z = acc[a][2] + bo + xv.z;
                v.w = acc[a][3] + bo + xv.w;
                *(float4*)(out + (((size_t)(bIdx * 64 + c) * 2048 + t) << 6) + j0) = v;
            }
        }
        __syncthreads();   // protect xs before next iteration's load
    }
}

extern "C" void kernel_launch(void* const* d_in, const int* in_sizes, int n_in,
                              void* d_out, int out_size) {
    const float* x       = (const float*)d_in[0];
    const float* w_g     = (const float*)d_in[1];
    const float* b_g     = (const float*)d_in[2];
    const float* w_theta = (const float*)d_in[3];
    const float* b_theta = (const float*)d_in[4];
    const float* w_phi   = (const float*)d_in[5];
    const float* b_phi   = (const float*)d_in[6];
    const float* proj    = (const float*)d_in[7];
    const float* w_out   = (const float*)d_in[8];
    const float* b_out   = (const float*)d_in[9];
    float* out = (float*)d_out;

    prep_kernel<<<1, 256>>>(w_theta, b_theta, w_phi, b_phi, proj);

    cudaFuncSetAttribute(tnl_kernel, cudaFuncAttributeMaxDynamicSharedMemorySize, SMEM_BYTES);
    // grid: 8 batches * (2048 / TT) t-chunks = 2048 CTAs
    tnl_kernel<<<8 * (2048 / TT), 256, SMEM_BYTES>>>(x, w_g, b_g, w_out, b_out, out);
}